// round 9
// baseline (speedup 1.0000x reference)
#include <cuda_runtime.h>
#include <cstdint>

#define NQ   512
#define SS   2048
#define DD   128
#define TOPK 32
#define CLS  1000

#define GROUPS    16          // 512 queries / 32
#define TILES_PG  18          // 16 cls tiles (64 cols) + 2 rec tiles (64 cols)

__device__ float g_summary[NQ * DD];
__device__ unsigned int g_ctr[GROUPS];   // zero-initialized; monotonic across replays

// dynamic smem pool: 12672 floats = 50688 B
//   attn phase: [0,8192) kring  [8192,10240) logits
//               [10240,11264) hist(uint)  [11264,11520) sge(uint)
//   gemm phase: [0,4224) As (32x132)  [4224,12672) Bs (64x132)
#define SMEM_FLOATS 12672

__device__ __forceinline__ float warp_sum(float v) {
    #pragma unroll
    for (int o = 16; o > 0; o >>= 1) v += __shfl_xor_sync(0xffffffffu, v, o);
    return v;
}

__device__ __forceinline__ void cp_async16(void* smem, const void* gmem) {
    uint32_t s = (uint32_t)__cvta_generic_to_shared(smem);
    asm volatile("cp.async.cg.shared.global [%0], [%1], 16;" :: "r"(s), "l"(gmem));
}

__device__ __forceinline__ uint32_t fmono(float x) {
    uint32_t b = __float_as_uint(x);
    return (b & 0x80000000u) ? ~b : (b | 0x80000000u);
}

__global__ __launch_bounds__(256, 4) void attn_fused_kernel(
    const float* __restrict__ q,
    const float* __restrict__ Kmat,
    const float* __restrict__ Vmat,
    const float* __restrict__ W_cls, const float* __restrict__ b_cls,
    const float* __restrict__ W_rec, const float* __restrict__ b_rec,
    float* __restrict__ cls_out,
    float* __restrict__ rec_out,
    float* __restrict__ weights_out)
{
    extern __shared__ __align__(16) float sp[];
    float*    logits = sp + 8192;
    uint32_t* hist   = (uint32_t*)(sp + 10240);
    uint32_t* sge    = (uint32_t*)(sp + 11264);

    __shared__ uint32_t wsum[8];
    __shared__ int   s_topi[TOPK];
    __shared__ float s_w[TOPK];
    __shared__ int   eqbuf[64];
    __shared__ uint32_t s_prefix;
    __shared__ int   s_need, cA, cE;
    __shared__ uint32_t s_target;

    const int n    = blockIdx.x;
    const int tid  = threadIdx.x;
    const int warp = tid >> 5;
    const int lane = tid & 31;
    const int row4 = lane >> 3;
    const int g8   = lane & 7;

    const float scale = 0.08838834764831845f; // 1/sqrt(128)

    // =========================== PHASE 1: attention ===========================
    float4 qf[4];
    {
        const float* qrow = q + (size_t)n * DD;
        #pragma unroll
        for (int j = 0; j < 4; j++)
            qf[j] = *reinterpret_cast<const float4*>(qrow + g8 * 4 + j * 32);
    }

    const float* __restrict__ Ksrc = Kmat + ((size_t)n * SS + warp * 256) * DD;
    float* __restrict__ lwarp = logits + warp * 256;

    #define K1_ISSUE(t)                                                        \
        do {                                                                   \
            float* _dst = sp + (warp * 2 + ((t) & 1)) * 512;                   \
            const float* _src = Ksrc + (size_t)(t) * 4 * DD;                   \
            _Pragma("unroll")                                                  \
            for (int _i = 0; _i < 4; _i++)                                     \
                cp_async16(&_dst[(lane + 32 * _i) * 4],                        \
                           _src + (lane + 32 * _i) * 4);                       \
            asm volatile("cp.async.commit_group;");                            \
        } while (0)

    K1_ISSUE(0);
    K1_ISSUE(1);

    #pragma unroll 1
    for (int t = 0; t < 64; t++) {
        if (t + 1 < 64) asm volatile("cp.async.wait_group 1;");
        else            asm volatile("cp.async.wait_group 0;");
        __syncwarp();

        const float* kb = sp + (warp * 2 + (t & 1)) * 512 + row4 * DD;
        float p = 0.f;
        #pragma unroll
        for (int j = 0; j < 4; j++) {
            float4 kv = *reinterpret_cast<const float4*>(kb + g8 * 4 + j * 32);
            p += qf[j].x * kv.x + qf[j].y * kv.y + qf[j].z * kv.z + qf[j].w * kv.w;
        }
        p += __shfl_xor_sync(0xffffffffu, p, 1);
        p += __shfl_xor_sync(0xffffffffu, p, 2);
        p += __shfl_xor_sync(0xffffffffu, p, 4);
        if (g8 == 0) lwarp[t * 4 + row4] = p * scale;
        __syncwarp();

        if (t + 2 < 64) K1_ISSUE(t + 2);
    }
    #undef K1_ISSUE

    if (tid == 0) { s_prefix = 0; s_need = TOPK; cA = 0; cE = 0; }
    __syncthreads();

    uint32_t u[8];
    #pragma unroll
    for (int j = 0; j < 8; j++) u[j] = fmono(logits[tid + 256 * j]);

    // ---- radix select top-32 (4 x 8-bit rounds) ----
    #pragma unroll 1
    for (int r = 0; r < 4; r++) {
        const int sh = 24 - 8 * r;
        #pragma unroll
        for (int b = 0; b < 4; b++) hist[b * 256 + tid] = 0;
        __syncthreads();
        const uint32_t pfx  = s_prefix;
        const int      need = s_need;
        #pragma unroll
        for (int j = 0; j < 8; j++) {
            uint32_t uu = u[j];
            bool ok = (r == 0) || ((uu >> (sh + 8)) == pfx);
            if (ok) atomicAdd(&hist[(warp & 3) * 256 + ((uu >> sh) & 255u)], 1u);
        }
        __syncthreads();
        uint32_t v = hist[tid] + hist[256 + tid] + hist[512 + tid] + hist[768 + tid];
        #pragma unroll
        for (int o = 1; o < 32; o <<= 1) {
            uint32_t t2 = __shfl_down_sync(0xffffffffu, v, o);
            if (lane + o < 32) v += t2;
        }
        if (lane == 0) wsum[warp] = v;
        __syncthreads();
        uint32_t tail = 0;
        #pragma unroll
        for (int w = 0; w < 8; w++) if (w > warp) tail += wsum[w];
        uint32_t ge = v + tail;
        sge[tid] = ge;
        __syncthreads();
        uint32_t ge_next = (tid == 255) ? 0u : sge[tid + 1];
        if (ge >= (uint32_t)need && ge_next < (uint32_t)need) {
            s_prefix = (pfx << 8) | (uint32_t)tid;
            s_need   = need - (int)ge_next;
        }
        __syncthreads();
    }

    const uint32_t ustar  = s_prefix;
    const int      needEq = s_need;

    #pragma unroll
    for (int j = 0; j < 8; j++) {
        uint32_t uu = u[j];
        if (uu > ustar) {
            int p = atomicAdd(&cA, 1);
            if (p < TOPK) s_topi[p] = tid + 256 * j;
        } else if (uu == ustar) {
            int p = atomicAdd(&cE, 1);
            if (p < 64) eqbuf[p] = tid + 256 * j;
        }
    }
    __syncthreads();

    if (warp == 0) {
        const int m = min(cA, TOPK - needEq);
        int E = min(cE, 64);
        int a  = (lane      < E) ? eqbuf[lane]      : 0x7FFFFFFF;
        int b2 = (lane + 32 < E) ? eqbuf[lane + 32] : 0x7FFFFFFF;
        #pragma unroll 1
        for (int t = 0; t < needEq; t++) {
            int mn = min(a, b2);
            #pragma unroll
            for (int o = 16; o > 0; o >>= 1)
                mn = min(mn, __shfl_xor_sync(0xffffffffu, mn, o));
            if (a == mn)       a  = 0x7FFFFFFF;
            else if (b2 == mn) b2 = 0x7FFFFFFF;
            if (lane == 0) s_topi[m + t] = mn;
        }
        __syncwarp();

        float val = logits[s_topi[lane]];
        float mx = val;
        #pragma unroll
        for (int o = 16; o > 0; o >>= 1)
            mx = fmaxf(mx, __shfl_xor_sync(0xffffffffu, mx, o));
        float e = expf(val - mx);
        float denom = warp_sum(e);
        s_w[lane] = e / denom;
    }
    __syncthreads();

    // V gather + zero logits
    float acc = 0.f;
    if (tid < DD) {
        #pragma unroll
        for (int i = 0; i < TOPK; i++)
            acc += s_w[i] * Vmat[((size_t)n * SS + s_topi[i]) * DD + tid];
    }
    {
        float4 z = make_float4(0.f, 0.f, 0.f, 0.f);
        float4* l4 = reinterpret_cast<float4*>(logits);
        #pragma unroll
        for (int i = tid; i < SS / 4; i += 256) l4[i] = z;
    }
    __syncthreads();

    if (tid < TOPK) logits[s_topi[tid]] = s_w[tid];
    if (tid < DD)   g_summary[n * DD + tid] = acc;
    __syncthreads();

    {
        const float4* src = reinterpret_cast<const float4*>(logits);
        float4* dst = reinterpret_cast<float4*>(weights_out + (size_t)n * SS);
        #pragma unroll
        for (int i = tid; i < SS / 4; i += 256) dst[i] = src[i];
    }
    __syncthreads();   // logits region will be reused as Bs

    // ======================= PHASE 2: group barrier =======================
    const int grp  = n >> 5;     // 16 groups of 32 queries
    const int tile = n & 31;     // worker id within group

    if (tid == 0) {
        __threadfence();         // publish g_summary
        uint32_t ticket = atomicAdd(&g_ctr[grp], 1u);
        s_target = (ticket / 32u + 1u) * 32u;   // replay-safe generation target
    }
    __syncthreads();

    if (tile >= TILES_PG) return;   // arrived; no gemm work

    if (tid == 0) {
        const uint32_t tgt = s_target;
        while (atomicAdd(&g_ctr[grp], 0u) < tgt) __nanosleep(64);
        __threadfence();
    }
    __syncthreads();

    // ======================= PHASE 3: readout tile =======================
    // tile < 16: cls columns [tile*64, +64);  tile 16/17: rec columns [(tile-16)*64, +64)
    const float* W;  const float* bias;  float* out;  int C;  int cTile;
    if (tile < 16) { W = W_cls; bias = b_cls; out = cls_out; C = CLS; cTile = tile * 64; }
    else           { W = W_rec; bias = b_rec; out = rec_out; C = DD;  cTile = (tile - 16) * 64; }
    const int nBase = grp * 32;

    float* As = sp;            // 32 x 132
    float* Bs = sp + 4224;     // 64 x 132

    // stage A (1024 16B chunks) + B (2048 chunks) via cp.async
    #pragma unroll
    for (int i = 0; i < 4; i++) {
        int c  = tid + i * 256;
        int rr = c >> 5, kq = c & 31;
        cp_async16(&As[rr * 132 + kq * 4],
                   g_summary + (size_t)(nBase + rr) * DD + kq * 4);
    }
    #pragma unroll
    for (int i = 0; i < 8; i++) {
        int c  = tid + i * 256;
        int rr = c >> 5, kq = c & 31;
        int cg = cTile + rr;
        if (cg < C)
            cp_async16(&Bs[rr * 132 + kq * 4], W + (size_t)cg * DD + kq * 4);
        else
            *reinterpret_cast<float4*>(&Bs[rr * 132 + kq * 4]) =
                make_float4(0.f, 0.f, 0.f, 0.f);
    }
    asm volatile("cp.async.commit_group;");
    asm volatile("cp.async.wait_group 0;");
    __syncthreads();

    const int tx = tid & 15;    // c within 16-col stripes
    const int ty = tid >> 4;    // n pair
    const float4* A0 = reinterpret_cast<const float4*>(As + (ty * 2 + 0) * 132);
    const float4* A1 = reinterpret_cast<const float4*>(As + (ty * 2 + 1) * 132);
    const float4* B0 = reinterpret_cast<const float4*>(Bs + ( 0 + tx) * 132);
    const float4* B1 = reinterpret_cast<const float4*>(Bs + (16 + tx) * 132);
    const float4* B2 = reinterpret_cast<const float4*>(Bs + (32 + tx) * 132);
    const float4* B3 = reinterpret_cast<const float4*>(Bs + (48 + tx) * 132);

    float a00=0.f,a01=0.f,a02=0.f,a03=0.f;
    float a10=0.f,a11=0.f,a12=0.f,a13=0.f;
    #pragma unroll 8
    for (int kq = 0; kq < 32; kq++) {
        float4 x0 = A0[kq], x1 = A1[kq];
        float4 y0 = B0[kq], y1 = B1[kq], y2 = B2[kq], y3 = B3[kq];
        a00 += x0.x*y0.x + x0.y*y0.y + x0.z*y0.z + x0.w*y0.w;
        a01 += x0.x*y1.x + x0.y*y1.y + x0.z*y1.z + x0.w*y1.w;
        a02 += x0.x*y2.x + x0.y*y2.y + x0.z*y2.z + x0.w*y2.w;
        a03 += x0.x*y3.x + x0.y*y3.y + x0.z*y3.z + x0.w*y3.w;
        a10 += x1.x*y0.x + x1.y*y0.y + x1.z*y0.z + x1.w*y0.w;
        a11 += x1.x*y1.x + x1.y*y1.y + x1.z*y1.z + x1.w*y1.w;
        a12 += x1.x*y2.x + x1.y*y2.y + x1.z*y2.z + x1.w*y2.w;
        a13 += x1.x*y3.x + x1.y*y3.y + x1.z*y3.z + x1.w*y3.w;
    }

    const int n0 = nBase + ty * 2;
    float accs[2][4] = {{a00,a01,a02,a03},{a10,a11,a12,a13}};
    #pragma unroll
    for (int j = 0; j < 4; j++) {
        int cg = cTile + j * 16 + tx;
        if (cg < C) {
            float bb = __ldg(&bias[cg]);
            out[(size_t)(n0 + 0) * C + cg] = accs[0][j] + bb;
            out[(size_t)(n0 + 1) * C + cg] = accs[1][j] + bb;
        }
    }
}

extern "C" void kernel_launch(void* const* d_in, const int* in_sizes, int n_in,
                              void* d_out, int out_size) {
    const float* q     = (const float*)d_in[0];
    const float* Kmat  = (const float*)d_in[1];
    const float* Vmat  = (const float*)d_in[2];
    const float* W_cls = (const float*)d_in[3];
    const float* b_cls = (const float*)d_in[4];
    const float* W_rec = (const float*)d_in[5];
    const float* b_rec = (const float*)d_in[6];

    float* out = (float*)d_out;
    float* cls = out;
    float* rec = out + (size_t)NQ * CLS;
    float* wts = rec + (size_t)NQ * DD;

    const int smem_bytes = SMEM_FLOATS * 4;   // 50688
    cudaFuncSetAttribute(attn_fused_kernel,
                         cudaFuncAttributeMaxDynamicSharedMemorySize, smem_bytes);

    attn_fused_kernel<<<NQ, 256, smem_bytes>>>(
        q, Kmat, Vmat, W_cls, b_cls, W_rec, b_rec, cls, rec, wts);
}

// round 10
// speedup vs baseline: 1.0622x; 1.0622x over previous
#include <cuda_runtime.h>
#include <cstdint>

#define NQ   512
#define SS   2048
#define DD   128
#define TOPK 32
#define CLS  1000

__device__ float g_summary[NQ * DD];

__device__ __forceinline__ float warp_sum(float v) {
    #pragma unroll
    for (int o = 16; o > 0; o >>= 1) v += __shfl_xor_sync(0xffffffffu, v, o);
    return v;
}

__device__ __forceinline__ void cp_async16(void* smem, const void* gmem) {
    uint32_t s = (uint32_t)__cvta_generic_to_shared(smem);
    asm volatile("cp.async.cg.shared.global [%0], [%1], 16;" :: "r"(s), "l"(gmem));
}

// monotone map: float total order == uint32 order. no NaNs in this data.
__device__ __forceinline__ uint32_t fmono(float x) {
    uint32_t b = __float_as_uint(x);
    return (b & 0x80000000u) ? ~b : (b | 0x80000000u);
}

// ---------------------------------------------------------------------------
// Fused attention (identical to R8 — validated at 106.3 total):
// warp-autonomous cp.async K streaming, radix-select top-32, softmax,
// V gather, weights row.
// ---------------------------------------------------------------------------
__global__ __launch_bounds__(256) void attn_topk_kernel(
    const float* __restrict__ q,
    const float* __restrict__ Kmat,
    const float* __restrict__ Vmat,
    float* __restrict__ weights_out)
{
    const int n    = blockIdx.x;
    const int tid  = threadIdx.x;
    const int warp = tid >> 5;
    const int lane = tid & 31;
    const int row4 = lane >> 3;
    const int g    = lane & 7;

    __shared__ __align__(16) float kring[8][2][4 * DD];  // 32 KB
    __shared__ float logits[SS];                         // 8 KB
    __shared__ uint32_t hist[4][256];                    // 4 KB
    __shared__ uint32_t sge[256];                        // 1 KB
    __shared__ uint32_t wsum[8];
    __shared__ int   s_topi[TOPK];
    __shared__ float s_w[TOPK];
    __shared__ int   eqbuf[64];
    __shared__ uint32_t s_prefix;
    __shared__ int   s_need, cA, cE;

    const float scale = 0.08838834764831845f; // 1/sqrt(128)

    float4 qf[4];
    {
        const float* qrow = q + (size_t)n * DD;
        #pragma unroll
        for (int j = 0; j < 4; j++)
            qf[j] = *reinterpret_cast<const float4*>(qrow + g * 4 + j * 32);
    }

    const float* __restrict__ Ksrc = Kmat + ((size_t)n * SS + warp * 256) * DD;
    float* __restrict__ lwarp = logits + warp * 256;

    #define K1_ISSUE(t)                                                        \
        do {                                                                   \
            float* _dst = kring[warp][(t) & 1];                                \
            const float* _src = Ksrc + (size_t)(t) * 4 * DD;                   \
            _Pragma("unroll")                                                  \
            for (int _i = 0; _i < 4; _i++)                                     \
                cp_async16(&_dst[(lane + 32 * _i) * 4],                        \
                           _src + (lane + 32 * _i) * 4);                       \
            asm volatile("cp.async.commit_group;");                            \
        } while (0)

    K1_ISSUE(0);
    K1_ISSUE(1);

    #pragma unroll 1
    for (int t = 0; t < 64; t++) {
        if (t + 1 < 64) asm volatile("cp.async.wait_group 1;");
        else            asm volatile("cp.async.wait_group 0;");
        __syncwarp();

        const float* kb = &kring[warp][t & 1][row4 * DD];
        float p = 0.f;
        #pragma unroll
        for (int j = 0; j < 4; j++) {
            float4 kv = *reinterpret_cast<const float4*>(kb + g * 4 + j * 32);
            p += qf[j].x * kv.x + qf[j].y * kv.y + qf[j].z * kv.z + qf[j].w * kv.w;
        }
        p += __shfl_xor_sync(0xffffffffu, p, 1);
        p += __shfl_xor_sync(0xffffffffu, p, 2);
        p += __shfl_xor_sync(0xffffffffu, p, 4);
        if (g == 0) lwarp[t * 4 + row4] = p * scale;
        __syncwarp();

        if (t + 2 < 64) K1_ISSUE(t + 2);
    }
    #undef K1_ISSUE

    if (tid == 0) { s_prefix = 0; s_need = TOPK; cA = 0; cE = 0; }
    __syncthreads();

    uint32_t u[8];
    #pragma unroll
    for (int j = 0; j < 8; j++) u[j] = fmono(logits[tid + 256 * j]);

    #pragma unroll 1
    for (int r = 0; r < 4; r++) {
        const int sh = 24 - 8 * r;
        #pragma unroll
        for (int b = 0; b < 4; b++) hist[b][tid] = 0;
        __syncthreads();
        const uint32_t pfx  = s_prefix;
        const int      need = s_need;
        #pragma unroll
        for (int j = 0; j < 8; j++) {
            uint32_t uu = u[j];
            bool ok = (r == 0) || ((uu >> (sh + 8)) == pfx);
            if (ok) atomicAdd(&hist[warp & 3][(uu >> sh) & 255u], 1u);
        }
        __syncthreads();
        uint32_t v = hist[0][tid] + hist[1][tid] + hist[2][tid] + hist[3][tid];
        #pragma unroll
        for (int o = 1; o < 32; o <<= 1) {
            uint32_t t2 = __shfl_down_sync(0xffffffffu, v, o);
            if (lane + o < 32) v += t2;
        }
        if (lane == 0) wsum[warp] = v;
        __syncthreads();
        uint32_t tail = 0;
        #pragma unroll
        for (int w = 0; w < 8; w++) if (w > warp) tail += wsum[w];
        uint32_t ge = v + tail;
        sge[tid] = ge;
        __syncthreads();
        uint32_t ge_next = (tid == 255) ? 0u : sge[tid + 1];
        if (ge >= (uint32_t)need && ge_next < (uint32_t)need) {
            s_prefix = (pfx << 8) | (uint32_t)tid;
            s_need   = need - (int)ge_next;
        }
        __syncthreads();
    }

    const uint32_t ustar  = s_prefix;
    const int      needEq = s_need;

    #pragma unroll
    for (int j = 0; j < 8; j++) {
        uint32_t uu = u[j];
        if (uu > ustar) {
            int p = atomicAdd(&cA, 1);
            if (p < TOPK) s_topi[p] = tid + 256 * j;
        } else if (uu == ustar) {
            int p = atomicAdd(&cE, 1);
            if (p < 64) eqbuf[p] = tid + 256 * j;
        }
    }
    __syncthreads();

    if (warp == 0) {
        const int m = min(cA, TOPK - needEq);
        int E = min(cE, 64);
        int a  = (lane      < E) ? eqbuf[lane]      : 0x7FFFFFFF;
        int b2 = (lane + 32 < E) ? eqbuf[lane + 32] : 0x7FFFFFFF;
        #pragma unroll 1
        for (int t = 0; t < needEq; t++) {
            int mn = min(a, b2);
            #pragma unroll
            for (int o = 16; o > 0; o >>= 1)
                mn = min(mn, __shfl_xor_sync(0xffffffffu, mn, o));
            if (a == mn)       a  = 0x7FFFFFFF;
            else if (b2 == mn) b2 = 0x7FFFFFFF;
            if (lane == 0) s_topi[m + t] = mn;
        }
        __syncwarp();

        float val = logits[s_topi[lane]];
        float mx = val;
        #pragma unroll
        for (int o = 16; o > 0; o >>= 1)
            mx = fmaxf(mx, __shfl_xor_sync(0xffffffffu, mx, o));
        float e = expf(val - mx);
        float denom = warp_sum(e);
        s_w[lane] = e / denom;
    }
    __syncthreads();

    float acc = 0.f;
    if (tid < DD) {
        #pragma unroll
        for (int i = 0; i < TOPK; i++)
            acc += s_w[i] * Vmat[((size_t)n * SS + s_topi[i]) * DD + tid];
    }
    {
        float4 z = make_float4(0.f, 0.f, 0.f, 0.f);
        float4* l4 = reinterpret_cast<float4*>(logits);
        #pragma unroll
        for (int i = tid; i < SS / 4; i += 256) l4[i] = z;
    }
    __syncthreads();

    if (tid < TOPK) logits[s_topi[tid]] = s_w[tid];
    if (tid < DD)   g_summary[n * DD + tid] = acc;
    __syncthreads();

    {
        const float4* src = reinterpret_cast<const float4*>(logits);
        float4* dst = reinterpret_cast<float4*>(weights_out + (size_t)n * SS);
        #pragma unroll
        for (int i = tid; i < SS / 4; i += 256) dst[i] = src[i];
    }
}

// ---------------------------------------------------------------------------
// Readout GEMMs, register-blocked: 64x64 tile, 256 threads, 4x4 micro-tile
// with c-striping (c = 16j + tx). Full K=128 staged once via cp.async.
// 2 B/FMA through the smem crossbar (vs 3 B/FMA before) and A-loads
// broadcast; B-loads conflict-free via odd float4 row stride (33).
// grid (18, 8): bx<16 -> cls (C=1000), bx 16/17 -> rec (C=128).
// ---------------------------------------------------------------------------
#define GR_STRIDE 132   // floats per row = 33 float4 (odd -> conflict-free)

__global__ __launch_bounds__(256) void readout_gemm(
    const float* __restrict__ Wc, const float* __restrict__ bc, float* __restrict__ outc,
    const float* __restrict__ Wr, const float* __restrict__ br, float* __restrict__ outr)
{
    extern __shared__ __align__(16) float sm[];
    float* As = sm;                    // 64 x 132
    float* Bs = sm + 64 * GR_STRIDE;   // 64 x 132

    const float* W;  const float* bias;  float* out;  int C;  int cTile;
    if (blockIdx.x < 16) { W = Wc; bias = bc; out = outc; C = CLS; cTile = blockIdx.x * 64; }
    else                 { W = Wr; bias = br; out = outr; C = DD;  cTile = (blockIdx.x - 16) * 64; }

    const int tid   = threadIdx.x;
    const int nTile = blockIdx.y * 64;

    // stage A and B: 2048 16B chunks each, 8 per thread per matrix
    #pragma unroll
    for (int i = 0; i < 8; i++) {
        int c  = tid + i * 256;      // 0..2047
        int rr = c >> 5;             // 0..63
        int kq = c & 31;             // float4 within row
        cp_async16(&As[rr * GR_STRIDE + kq * 4],
                   g_summary + (size_t)(nTile + rr) * DD + kq * 4);
        int cg = cTile + rr;
        if (cg < C)
            cp_async16(&Bs[rr * GR_STRIDE + kq * 4], W + (size_t)cg * DD + kq * 4);
        else
            *reinterpret_cast<float4*>(&Bs[rr * GR_STRIDE + kq * 4]) =
                make_float4(0.f, 0.f, 0.f, 0.f);
    }
    asm volatile("cp.async.commit_group;");
    asm volatile("cp.async.wait_group 0;");
    __syncthreads();

    const int tx = tid & 15;   // c lane within each 16-col stripe
    const int ty = tid >> 4;   // n quad: rows ty*4 .. ty*4+3

    const float4* A0 = reinterpret_cast<const float4*>(As + (ty * 4 + 0) * GR_STRIDE);
    const float4* A1 = reinterpret_cast<const float4*>(As + (ty * 4 + 1) * GR_STRIDE);
    const float4* A2 = reinterpret_cast<const float4*>(As + (ty * 4 + 2) * GR_STRIDE);
    const float4* A3 = reinterpret_cast<const float4*>(As + (ty * 4 + 3) * GR_STRIDE);
    const float4* B0 = reinterpret_cast<const float4*>(Bs + ( 0 + tx) * GR_STRIDE);
    const float4* B1 = reinterpret_cast<const float4*>(Bs + (16 + tx) * GR_STRIDE);
    const float4* B2 = reinterpret_cast<const float4*>(Bs + (32 + tx) * GR_STRIDE);
    const float4* B3 = reinterpret_cast<const float4*>(Bs + (48 + tx) * GR_STRIDE);

    float acc[4][4];
    #pragma unroll
    for (int i = 0; i < 4; i++)
        #pragma unroll
        for (int j = 0; j < 4; j++) acc[i][j] = 0.f;

    #pragma unroll 4
    for (int kq = 0; kq < 32; kq++) {
        float4 a[4] = {A0[kq], A1[kq], A2[kq], A3[kq]};
        float4 b[4] = {B0[kq], B1[kq], B2[kq], B3[kq]};
        #pragma unroll
        for (int i = 0; i < 4; i++)
            #pragma unroll
            for (int j = 0; j < 4; j++)
                acc[i][j] += a[i].x * b[j].x + a[i].y * b[j].y +
                             a[i].z * b[j].z + a[i].w * b[j].w;
    }

    #pragma unroll
    for (int i = 0; i < 4; i++) {
        int nn = nTile + ty * 4 + i;
        #pragma unroll
        for (int j = 0; j < 4; j++) {
            int cg = cTile + j * 16 + tx;
            if (cg < C)
                out[(size_t)nn * C + cg] = acc[i][j] + __ldg(&bias[cg]);
        }
    }
}

extern "C" void kernel_launch(void* const* d_in, const int* in_sizes, int n_in,
                              void* d_out, int out_size) {
    const float* q     = (const float*)d_in[0];
    const float* Kmat  = (const float*)d_in[1];
    const float* Vmat  = (const float*)d_in[2];
    const float* W_cls = (const float*)d_in[3];
    const float* b_cls = (const float*)d_in[4];
    const float* W_rec = (const float*)d_in[5];
    const float* b_rec = (const float*)d_in[6];

    float* out = (float*)d_out;
    float* cls = out;
    float* rec = out + (size_t)NQ * CLS;
    float* wts = rec + (size_t)NQ * DD;

    attn_topk_kernel<<<NQ, 256>>>(q, Kmat, Vmat, wts);

    const int gemm_smem = 2 * 64 * GR_STRIDE * 4;   // 67584 B
    static int attr_set = 0;
    if (!attr_set) {
        cudaFuncSetAttribute(readout_gemm,
                             cudaFuncAttributeMaxDynamicSharedMemorySize, gemm_smem);
        attr_set = 1;
    }
    readout_gemm<<<dim3(18, 8), 256, gemm_smem>>>(W_cls, b_cls, cls, W_rec, b_rec, rec);
}

// round 11
// speedup vs baseline: 1.0635x; 1.0013x over previous
#include <cuda_runtime.h>
#include <cstdint>

#define NQ   512
#define SS   2048
#define DD   128
#define TOPK 32
#define CLS  1000

__device__ float g_summary[NQ * DD];

__device__ __forceinline__ float warp_sum(float v) {
    #pragma unroll
    for (int o = 16; o > 0; o >>= 1) v += __shfl_xor_sync(0xffffffffu, v, o);
    return v;
}

__device__ __forceinline__ void cp_async16(void* smem, const void* gmem) {
    uint32_t s = (uint32_t)__cvta_generic_to_shared(smem);
    asm volatile("cp.async.cg.shared.global [%0], [%1], 16;" :: "r"(s), "l"(gmem));
}

// monotone map: float total order == uint32 order. no NaNs in this data.
__device__ __forceinline__ uint32_t fmono(float x) {
    uint32_t b = __float_as_uint(x);
    return (b & 0x80000000u) ? ~b : (b | 0x80000000u);
}

// ---------------------------------------------------------------------------
// Fused attention (R8/R10-validated) + PDL trigger once g_summary is visible.
// ---------------------------------------------------------------------------
__global__ __launch_bounds__(256) void attn_topk_kernel(
    const float* __restrict__ q,
    const float* __restrict__ Kmat,
    const float* __restrict__ Vmat,
    float* __restrict__ weights_out)
{
    const int n    = blockIdx.x;
    const int tid  = threadIdx.x;
    const int warp = tid >> 5;
    const int lane = tid & 31;
    const int row4 = lane >> 3;
    const int g    = lane & 7;

    __shared__ __align__(16) float kring[8][2][4 * DD];  // 32 KB
    __shared__ float logits[SS];                         // 8 KB
    __shared__ uint32_t hist[4][256];                    // 4 KB
    __shared__ uint32_t sge[256];                        // 1 KB
    __shared__ uint32_t wsum[8];
    __shared__ int   s_topi[TOPK];
    __shared__ float s_w[TOPK];
    __shared__ int   eqbuf[64];
    __shared__ uint32_t s_prefix;
    __shared__ int   s_need, cA, cE;

    const float scale = 0.08838834764831845f; // 1/sqrt(128)

    float4 qf[4];
    {
        const float* qrow = q + (size_t)n * DD;
        #pragma unroll
        for (int j = 0; j < 4; j++)
            qf[j] = *reinterpret_cast<const float4*>(qrow + g * 4 + j * 32);
    }

    const float* __restrict__ Ksrc = Kmat + ((size_t)n * SS + warp * 256) * DD;
    float* __restrict__ lwarp = logits + warp * 256;

    #define K1_ISSUE(t)                                                        \
        do {                                                                   \
            float* _dst = kring[warp][(t) & 1];                                \
            const float* _src = Ksrc + (size_t)(t) * 4 * DD;                   \
            _Pragma("unroll")                                                  \
            for (int _i = 0; _i < 4; _i++)                                     \
                cp_async16(&_dst[(lane + 32 * _i) * 4],                        \
                           _src + (lane + 32 * _i) * 4);                       \
            asm volatile("cp.async.commit_group;");                            \
        } while (0)

    K1_ISSUE(0);
    K1_ISSUE(1);

    #pragma unroll 1
    for (int t = 0; t < 64; t++) {
        if (t + 1 < 64) asm volatile("cp.async.wait_group 1;");
        else            asm volatile("cp.async.wait_group 0;");
        __syncwarp();

        const float* kb = &kring[warp][t & 1][row4 * DD];
        float p = 0.f;
        #pragma unroll
        for (int j = 0; j < 4; j++) {
            float4 kv = *reinterpret_cast<const float4*>(kb + g * 4 + j * 32);
            p += qf[j].x * kv.x + qf[j].y * kv.y + qf[j].z * kv.z + qf[j].w * kv.w;
        }
        p += __shfl_xor_sync(0xffffffffu, p, 1);
        p += __shfl_xor_sync(0xffffffffu, p, 2);
        p += __shfl_xor_sync(0xffffffffu, p, 4);
        if (g == 0) lwarp[t * 4 + row4] = p * scale;
        __syncwarp();

        if (t + 2 < 64) K1_ISSUE(t + 2);
    }
    #undef K1_ISSUE

    if (tid == 0) { s_prefix = 0; s_need = TOPK; cA = 0; cE = 0; }
    __syncthreads();

    uint32_t u[8];
    #pragma unroll
    for (int j = 0; j < 8; j++) u[j] = fmono(logits[tid + 256 * j]);

    #pragma unroll 1
    for (int r = 0; r < 4; r++) {
        const int sh = 24 - 8 * r;
        #pragma unroll
        for (int b = 0; b < 4; b++) hist[b][tid] = 0;
        __syncthreads();
        const uint32_t pfx  = s_prefix;
        const int      need = s_need;
        #pragma unroll
        for (int j = 0; j < 8; j++) {
            uint32_t uu = u[j];
            bool ok = (r == 0) || ((uu >> (sh + 8)) == pfx);
            if (ok) atomicAdd(&hist[warp & 3][(uu >> sh) & 255u], 1u);
        }
        __syncthreads();
        uint32_t v = hist[0][tid] + hist[1][tid] + hist[2][tid] + hist[3][tid];
        #pragma unroll
        for (int o = 1; o < 32; o <<= 1) {
            uint32_t t2 = __shfl_down_sync(0xffffffffu, v, o);
            if (lane + o < 32) v += t2;
        }
        if (lane == 0) wsum[warp] = v;
        __syncthreads();
        uint32_t tail = 0;
        #pragma unroll
        for (int w = 0; w < 8; w++) if (w > warp) tail += wsum[w];
        uint32_t ge = v + tail;
        sge[tid] = ge;
        __syncthreads();
        uint32_t ge_next = (tid == 255) ? 0u : sge[tid + 1];
        if (ge >= (uint32_t)need && ge_next < (uint32_t)need) {
            s_prefix = (pfx << 8) | (uint32_t)tid;
            s_need   = need - (int)ge_next;
        }
        __syncthreads();
    }

    const uint32_t ustar  = s_prefix;
    const int      needEq = s_need;

    #pragma unroll
    for (int j = 0; j < 8; j++) {
        uint32_t uu = u[j];
        if (uu > ustar) {
            int p = atomicAdd(&cA, 1);
            if (p < TOPK) s_topi[p] = tid + 256 * j;
        } else if (uu == ustar) {
            int p = atomicAdd(&cE, 1);
            if (p < 64) eqbuf[p] = tid + 256 * j;
        }
    }
    __syncthreads();

    if (warp == 0) {
        const int m = min(cA, TOPK - needEq);
        int E = min(cE, 64);
        int a  = (lane      < E) ? eqbuf[lane]      : 0x7FFFFFFF;
        int b2 = (lane + 32 < E) ? eqbuf[lane + 32] : 0x7FFFFFFF;
        #pragma unroll 1
        for (int t = 0; t < needEq; t++) {
            int mn = min(a, b2);
            #pragma unroll
            for (int o = 16; o > 0; o >>= 1)
                mn = min(mn, __shfl_xor_sync(0xffffffffu, mn, o));
            if (a == mn)       a  = 0x7FFFFFFF;
            else if (b2 == mn) b2 = 0x7FFFFFFF;
            if (lane == 0) s_topi[m + t] = mn;
        }
        __syncwarp();

        float val = logits[s_topi[lane]];
        float mx = val;
        #pragma unroll
        for (int o = 16; o > 0; o >>= 1)
            mx = fmaxf(mx, __shfl_xor_sync(0xffffffffu, mx, o));
        float e = expf(val - mx);
        float denom = warp_sum(e);
        s_w[lane] = e / denom;
    }
    __syncthreads();

    float acc = 0.f;
    if (tid < DD) {
        #pragma unroll
        for (int i = 0; i < TOPK; i++)
            acc += s_w[i] * Vmat[((size_t)n * SS + s_topi[i]) * DD + tid];
    }
    {
        float4 z = make_float4(0.f, 0.f, 0.f, 0.f);
        float4* l4 = reinterpret_cast<float4*>(logits);
        #pragma unroll
        for (int i = tid; i < SS / 4; i += 256) l4[i] = z;
    }
    __syncthreads();

    if (tid < TOPK) logits[s_topi[tid]] = s_w[tid];
    if (tid < DD)   g_summary[n * DD + tid] = acc;
    __syncthreads();

    // g_summary for this query is globally visible -> allow dependent launch.
    // (canonical publish pattern: block-wide sync, then one thread fences)
    if (tid == 0) {
        __threadfence();
        asm volatile("griddepcontrol.launch_dependents;");
    }

    // weights row writeout overlaps with the dependent GEMM's W staging
    {
        const float4* src = reinterpret_cast<const float4*>(logits);
        float4* dst = reinterpret_cast<float4*>(weights_out + (size_t)n * SS);
        #pragma unroll
        for (int i = tid; i < SS / 4; i += 256) dst[i] = src[i];
    }
}

// ---------------------------------------------------------------------------
// Readout GEMMs (R10 register-blocked, PDL-split staging):
// stage B (attn-independent) BEFORE griddepcontrol.wait, A after.
// 64x64 tile, 4x4 micro-tile c-striped, 2 B/FMA crossbar traffic.
// grid (18, 8): bx<16 -> cls (C=1000), bx 16/17 -> rec (C=128).
// ---------------------------------------------------------------------------
#define GR_STRIDE 132   // floats per row = 33 float4 (odd -> conflict-free)

__global__ __launch_bounds__(256) void readout_gemm(
    const float* __restrict__ Wc, const float* __restrict__ bc, float* __restrict__ outc,
    const float* __restrict__ Wr, const float* __restrict__ br, float* __restrict__ outr)
{
    extern __shared__ __align__(16) float sm[];
    float* As = sm;                    // 64 x 132
    float* Bs = sm + 64 * GR_STRIDE;   // 64 x 132

    const float* W;  const float* bias;  float* out;  int C;  int cTile;
    if (blockIdx.x < 16) { W = Wc; bias = bc; out = outc; C = CLS; cTile = blockIdx.x * 64; }
    else                 { W = Wr; bias = br; out = outr; C = DD;  cTile = (blockIdx.x - 16) * 64; }

    const int tid   = threadIdx.x;
    const int nTile = blockIdx.y * 64;

    // ---- stage B tile: independent of attention output ----
    #pragma unroll
    for (int i = 0; i < 8; i++) {
        int c  = tid + i * 256;      // 0..2047
        int rr = c >> 5;             // 0..63
        int kq = c & 31;
        int cg = cTile + rr;
        if (cg < C)
            cp_async16(&Bs[rr * GR_STRIDE + kq * 4], W + (size_t)cg * DD + kq * 4);
        else
            *reinterpret_cast<float4*>(&Bs[rr * GR_STRIDE + kq * 4]) =
                make_float4(0.f, 0.f, 0.f, 0.f);
    }
    asm volatile("cp.async.commit_group;");

    // ---- wait for attention grid to publish g_summary ----
    asm volatile("griddepcontrol.wait;");

    // ---- stage A tile (g_summary) ----
    #pragma unroll
    for (int i = 0; i < 8; i++) {
        int c  = tid + i * 256;
        int rr = c >> 5;
        int kq = c & 31;
        cp_async16(&As[rr * GR_STRIDE + kq * 4],
                   g_summary + (size_t)(nTile + rr) * DD + kq * 4);
    }
    asm volatile("cp.async.commit_group;");
    asm volatile("cp.async.wait_group 0;");
    __syncthreads();

    const int tx = tid & 15;   // c lane within each 16-col stripe
    const int ty = tid >> 4;   // n quad

    const float4* A0 = reinterpret_cast<const float4*>(As + (ty * 4 + 0) * GR_STRIDE);
    const float4* A1 = reinterpret_cast<const float4*>(As + (ty * 4 + 1) * GR_STRIDE);
    const float4* A2 = reinterpret_cast<const float4*>(As + (ty * 4 + 2) * GR_STRIDE);
    const float4* A3 = reinterpret_cast<const float4*>(As + (ty * 4 + 3) * GR_STRIDE);
    const float4* B0 = reinterpret_cast<const float4*>(Bs + ( 0 + tx) * GR_STRIDE);
    const float4* B1 = reinterpret_cast<const float4*>(Bs + (16 + tx) * GR_STRIDE);
    const float4* B2 = reinterpret_cast<const float4*>(Bs + (32 + tx) * GR_STRIDE);
    const float4* B3 = reinterpret_cast<const float4*>(Bs + (48 + tx) * GR_STRIDE);

    float acc[4][4];
    #pragma unroll
    for (int i = 0; i < 4; i++)
        #pragma unroll
        for (int j = 0; j < 4; j++) acc[i][j] = 0.f;

    #pragma unroll 4
    for (int kq = 0; kq < 32; kq++) {
        float4 a[4] = {A0[kq], A1[kq], A2[kq], A3[kq]};
        float4 b[4] = {B0[kq], B1[kq], B2[kq], B3[kq]};
        #pragma unroll
        for (int i = 0; i < 4; i++)
            #pragma unroll
            for (int j = 0; j < 4; j++)
                acc[i][j] += a[i].x * b[j].x + a[i].y * b[j].y +
                             a[i].z * b[j].z + a[i].w * b[j].w;
    }

    #pragma unroll
    for (int i = 0; i < 4; i++) {
        int nn = nTile + ty * 4 + i;
        #pragma unroll
        for (int j = 0; j < 4; j++) {
            int cg = cTile + j * 16 + tx;
            if (cg < C)
                out[(size_t)nn * C + cg] = acc[i][j] + __ldg(&bias[cg]);
        }
    }
}

extern "C" void kernel_launch(void* const* d_in, const int* in_sizes, int n_in,
                              void* d_out, int out_size) {
    const float* q     = (const float*)d_in[0];
    const float* Kmat  = (const float*)d_in[1];
    const float* Vmat  = (const float*)d_in[2];
    const float* W_cls = (const float*)d_in[3];
    const float* b_cls = (const float*)d_in[4];
    const float* W_rec = (const float*)d_in[5];
    const float* b_rec = (const float*)d_in[6];

    float* out = (float*)d_out;
    float* cls = out;
    float* rec = out + (size_t)NQ * CLS;
    float* wts = rec + (size_t)NQ * DD;

    const int gemm_smem = 2 * 64 * GR_STRIDE * 4;   // 67584 B
    static int attr_set = 0;
    if (!attr_set) {
        cudaFuncSetAttribute(readout_gemm,
                             cudaFuncAttributeMaxDynamicSharedMemorySize, gemm_smem);
        attr_set = 1;
    }

    attn_topk_kernel<<<NQ, 256>>>(q, Kmat, Vmat, wts);

    // dependent launch: overlaps its W staging with the attention tail
    cudaLaunchConfig_t cfg = {};
    cfg.gridDim  = dim3(18, 8, 1);
    cfg.blockDim = dim3(256, 1, 1);
    cfg.dynamicSmemBytes = gemm_smem;
    cfg.stream = 0;
    cudaLaunchAttribute at[1];
    at[0].id = cudaLaunchAttributeProgrammaticStreamSerialization;
    at[0].val.programmaticStreamSerializationAllowed = 1;
    cfg.attrs = at;
    cfg.numAttrs = 1;
    cudaLaunchKernelEx(&cfg, readout_gemm, W_cls, b_cls, cls, W_rec, b_rec, rec);
}